// round 7
// baseline (speedup 1.0000x reference)
#include <cuda_runtime.h>
#include <cuda_fp16.h>
#include <math.h>
#include <stdint.h>

// ---------------- problem constants ----------------
#define BATCH   32
#define NTOK    1280
#define DIM     384
#define NHEAD   8
#define HDIM    48
#define NSRCH   1024
#define KVMIX   320
#define FFD     1536
#define ATT_SCALE 0.14433756729740643f   // 1/sqrt(48)

// ---------------- scratch (device globals; no allocation allowed) --------
__device__ float  g_xn [BATCH * NTOK * DIM];
__device__ float  g_x1 [BATCH * NTOK * DIM];
__device__ __half h_qtok[BATCH * NTOK * DIM];
__device__ __half h_ktok[BATCH * KVMIX * DIM];
__device__ __half h_vtok[BATCH * KVMIX * DIM];
__device__ __half h_Q  [BATCH * NTOK * DIM];
__device__ __half h_K  [BATCH * KVMIX * DIM];
__device__ __half h_V  [BATCH * KVMIX * DIM];
__device__ __half h_ln2[BATCH * NTOK * DIM];
__device__ __half h_ff [BATCH * NTOK * FFD];
__device__ __half h_wq [DIM * DIM];
__device__ __half h_wk [DIM * DIM];
__device__ __half h_wv [DIM * DIM];
__device__ __half h_w1 [FFD * DIM];
__device__ __half h_w2 [DIM * FFD];

// ================= small helpers =================
__device__ __forceinline__ uint32_t smem_u32(const void* p)
{
    uint32_t a;
    asm("{ .reg .u64 t; cvta.to.shared.u64 t, %1; cvt.u32.u64 %0, t; }"
        : "=r"(a) : "l"(p));
    return a;
}

__device__ __forceinline__ void cpasync16(uint32_t dst, const void* src)
{
    asm volatile("cp.async.cg.shared.global [%0], [%1], 16;"
                 :: "r"(dst), "l"(src));
}

__device__ __forceinline__ void ldm_x4(uint32_t* r, uint32_t addr)
{
    asm volatile("ldmatrix.sync.aligned.m8n8.x4.shared.b16 {%0,%1,%2,%3}, [%4];"
                 : "=r"(r[0]), "=r"(r[1]), "=r"(r[2]), "=r"(r[3]) : "r"(addr));
}

__device__ __forceinline__ void ldm_x4t(uint32_t* r, uint32_t addr)
{
    asm volatile("ldmatrix.sync.aligned.m8n8.x4.trans.shared.b16 {%0,%1,%2,%3}, [%4];"
                 : "=r"(r[0]), "=r"(r[1]), "=r"(r[2]), "=r"(r[3]) : "r"(addr));
}

__device__ __forceinline__ void mma16816(float* d, const uint32_t* a, const uint32_t* b)
{
    asm volatile(
        "mma.sync.aligned.m16n8k16.row.col.f32.f16.f16.f32 "
        "{%0,%1,%2,%3}, {%4,%5,%6,%7}, {%8,%9}, {%0,%1,%2,%3};"
        : "+f"(d[0]), "+f"(d[1]), "+f"(d[2]), "+f"(d[3])
        : "r"(a[0]), "r"(a[1]), "r"(a[2]), "r"(a[3]), "r"(b[0]), "r"(b[1]));
}

// ================= fp16 tensor-core GEMM (proj / FFN) =================
// C = A(MxK) * B(NxK)^T, fp16 in, fp32 acc.
// Block 128x128x32, 8 warps (4m x 2n), warp tile 32x64.
// All dims must divide tiles exactly (they do for every call site).
// EPI: 0 bias->half, 1 bias+gelu->half, 2 bias+res->float
#define BMH 128
#define BNH 128
#define BKH 32
#define LDS_A 40   // halfs per smem row (80B); chunk-xor swizzled

template<int EPI>
__global__ __launch_bounds__(256, 1)
void gemm_h(const __half* __restrict__ A, const __half* __restrict__ Bw,
            const float* __restrict__ bias, const float* __restrict__ res,
            void* __restrict__ Cv, int K, int Nn,
            int lda, int ldb, int ldc)
{
    __shared__ __half As[2][BMH * LDS_A];
    __shared__ __half Bs[2][BNH * LDS_A];

    int tid  = threadIdx.x;
    int warp = tid >> 5, lane = tid & 31;
    int wm = warp >> 1, wn = warp & 1;
    int cn = blockIdx.x * BNH;
    int cm = blockIdx.y * BMH;

    const __half* Ab = A  + (long)cm * lda;
    const __half* Bb = Bw + (long)cn * ldb;

    uint32_t sA[2] = { smem_u32(As[0]), smem_u32(As[1]) };
    uint32_t sB[2] = { smem_u32(Bs[0]), smem_u32(Bs[1]) };

    // 512 A-chunks + 512 B-chunks of 16B per stage; 256 threads x (2+2)
    auto fill = [&](int st, int kt) {
        int k0 = kt * BKH;
        #pragma unroll
        for (int i = 0; i < 2; i++) {
            int c = tid + i * 256;
            int row = c >> 2, ch = c & 3;
            uint32_t dst = sA[st] + (row * LDS_A + ((ch ^ (row & 3)) * 8)) * 2;
            cpasync16(dst, Ab + (long)row * lda + k0 + ch * 8);
        }
        #pragma unroll
        for (int i = 0; i < 2; i++) {
            int c = tid + i * 256;
            int n = c >> 2, ch = c & 3;
            uint32_t dst = sB[st] + (n * LDS_A + ((ch ^ (n & 3)) * 8)) * 2;
            cpasync16(dst, Bb + (long)n * ldb + k0 + ch * 8);
        }
        asm volatile("cp.async.commit_group;" ::: "memory");
    };

    int l15 = lane & 15, l7 = lane & 7, l3 = lane & 3;
    int achunk[2], bchunk[2];
    #pragma unroll
    for (int ks = 0; ks < 2; ks++) {
        achunk[ks] = (((lane >> 4) + 2 * ks) ^ l3) * 8;
        bchunk[ks] = ((((lane >> 3) & 1) + 2 * ks) ^ l3) * 8;
    }
    int arow[2], brow[4];
    #pragma unroll
    for (int f = 0; f < 2; f++)
        arow[f] = (wm * 32 + f * 16 + l15) * LDS_A;
    #pragma unroll
    for (int p = 0; p < 4; p++)
        brow[p] = (wn * 64 + p * 16 + ((lane >> 4) & 1) * 8 + l7) * LDS_A;

    float acc[2][8][4];
    #pragma unroll
    for (int i = 0; i < 2; i++)
        #pragma unroll
        for (int j = 0; j < 8; j++)
            #pragma unroll
            for (int q = 0; q < 4; q++) acc[i][j][q] = 0.f;

    int T = K / BKH;
    fill(0, 0);

    for (int t = 0; t < T; t++) {
        int st = t & 1;
        if (t + 1 < T) fill(1 - st, t + 1);
        asm volatile("cp.async.wait_group %0;" :: "n"(1) : "memory");
        if (t + 1 >= T) asm volatile("cp.async.wait_group 0;" ::: "memory");
        __syncthreads();

        #pragma unroll
        for (int ks = 0; ks < 2; ks++) {
            uint32_t ar[2][4];
            #pragma unroll
            for (int f = 0; f < 2; f++)
                ldm_x4(ar[f], sA[st] + (arow[f] + achunk[ks]) * 2);
            #pragma unroll
            for (int p = 0; p < 4; p++) {
                uint32_t br[4];
                ldm_x4(br, sB[st] + (brow[p] + bchunk[ks]) * 2);
                #pragma unroll
                for (int mf = 0; mf < 2; mf++) {
                    mma16816(acc[mf][2 * p],     ar[mf], &br[0]);
                    mma16816(acc[mf][2 * p + 1], ar[mf], &br[2]);
                }
            }
        }
        __syncthreads();
    }

    int gid = lane >> 2, cpos = (lane & 3) * 2;
    #pragma unroll
    for (int mf = 0; mf < 2; mf++) {
        #pragma unroll
        for (int nf = 0; nf < 8; nf++) {
            int col = cn + wn * 64 + nf * 8 + cpos;
            long r0 = cm + wm * 32 + mf * 16 + gid;
            #pragma unroll
            for (int hh = 0; hh < 2; hh++) {
                long idx = (r0 + hh * 8) * (long)ldc + col;
                float v0 = acc[mf][nf][hh * 2 + 0];
                float v1 = acc[mf][nf][hh * 2 + 1];
                v0 += bias[col]; v1 += bias[col + 1];
                if (EPI == 1) { v0 *= normcdff(v0); v1 *= normcdff(v1); }
                if (EPI == 2) {
                    float2 r2 = *(const float2*)&res[idx];
                    v0 += r2.x; v1 += r2.y;
                    float2 o; o.x = v0; o.y = v1;
                    *(float2*)&((float*)Cv)[idx] = o;
                } else {
                    *(__half2*)&((__half*)Cv)[idx] = __floats2half2_rn(v0, v1);
                }
            }
        }
    }
}

// ================= fused flash attention (legacy mma) ====================
// One CTA = 128 query rows of one (batch, head). 4 warps, warp = 32 q rows.
// K/V tiles 64 x 48 (64-half rows, chunk-xor swizzle).
#define FA_LD 64   // halfs per smem row (128B)

__global__ __launch_bounds__(128)
void attn_fa(const __half* __restrict__ Q, const __half* __restrict__ Kh,
             const __half* __restrict__ Vh, const float* __restrict__ x,
             float* __restrict__ x1, int q_base, int kv_base, int kv_len)
{
    __shared__ __half Qs[128 * FA_LD];
    __shared__ __half Ks[64 * FA_LD];
    __shared__ __half Vs[64 * FA_LD];

    int tid = threadIdx.x;
    int warp = tid >> 5, lane = tid & 31;
    int gid = lane >> 2, tig = lane & 3;
    int b = blockIdx.z, h = blockIdx.y;
    int q0blk = blockIdx.x * 128;

    const __half* Qg = Q + ((long)b * NTOK + q_base + q0blk) * DIM + h * HDIM;
    const __half* Kg = Kh + ((long)b * KVMIX + kv_base) * DIM + h * HDIM;
    const __half* Vg = Vh + ((long)b * KVMIX + kv_base) * DIM + h * HDIM;

    uint32_t sQ = smem_u32(Qs), sK = smem_u32(Ks), sV = smem_u32(Vs);

    // load Q tile (128 rows x 6 chunks of 16B)
    {
        int row = tid;
        #pragma unroll
        for (int c = 0; c < 6; c++) {
            uint32_t dst = sQ + (row * FA_LD + ((c ^ (row & 7)) * 8)) * 2;
            cpasync16(dst, Qg + (long)row * DIM + c * 8);
        }
    }
    asm volatile("cp.async.commit_group;" ::: "memory");
    asm volatile("cp.async.wait_group 0;" ::: "memory");
    __syncthreads();

    // Q fragments: qa[ks][mf][4]
    uint32_t qa[3][2][4];
    {
        int qrow_base = warp * 32;
        #pragma unroll
        for (int ks = 0; ks < 3; ks++)
            #pragma unroll
            for (int mf = 0; mf < 2; mf++) {
                int row = qrow_base + mf * 16 + (lane & 15);
                int ch  = (ks * 2 + (lane >> 4)) ^ (row & 7);
                ldm_x4(qa[ks][mf], sQ + (row * FA_LD + ch * 8) * 2);
            }
    }

    float oa[2][6][4];
    #pragma unroll
    for (int i = 0; i < 2; i++)
        #pragma unroll
        for (int j = 0; j < 6; j++)
            #pragma unroll
            for (int q = 0; q < 4; q++) oa[i][j][q] = 0.f;
    float mrow[2][2] = { {-INFINITY, -INFINITY}, {-INFINITY, -INFINITY} };
    float lrow[2][2] = { {0.f, 0.f}, {0.f, 0.f} };

    int nc = kv_len >> 6;
    for (int c = 0; c < nc; c++) {
        __syncthreads();
        // load K, V tiles: 384 chunks each, 128 threads x 3
        #pragma unroll
        for (int i = 0; i < 3; i++) {
            int idx = tid * 3 + i;
            int row = idx / 6, ch = idx % 6;
            long go = ((long)(c * 64 + row)) * DIM + ch * 8;
            uint32_t sw = (row * FA_LD + ((ch ^ (row & 7)) * 8)) * 2;
            cpasync16(sK + sw, Kg + go);
            cpasync16(sV + sw, Vg + go);
        }
        asm volatile("cp.async.commit_group;" ::: "memory");
        asm volatile("cp.async.wait_group 0;" ::: "memory");
        __syncthreads();

        // S = Q K^T  (warp's 32 rows x 64 cols)
        float sa[2][8][4];
        #pragma unroll
        for (int i = 0; i < 2; i++)
            #pragma unroll
            for (int j = 0; j < 8; j++)
                #pragma unroll
                for (int q = 0; q < 4; q++) sa[i][j][q] = 0.f;

        #pragma unroll
        for (int ks = 0; ks < 3; ks++) {
            #pragma unroll
            for (int g = 0; g < 4; g++) {
                uint32_t kb[4];
                int row = g * 16 + (lane & 7) + ((lane >> 4) & 1) * 8;
                int ch  = (ks * 2 + ((lane >> 3) & 1)) ^ (row & 7);
                ldm_x4(kb, sK + (row * FA_LD + ch * 8) * 2);
                #pragma unroll
                for (int mf = 0; mf < 2; mf++) {
                    mma16816(sa[mf][2 * g],     qa[ks][mf], &kb[0]);
                    mma16816(sa[mf][2 * g + 1], qa[ks][mf], &kb[2]);
                }
            }
        }

        // online softmax
        #pragma unroll
        for (int mf = 0; mf < 2; mf++) {
            #pragma unroll
            for (int hh = 0; hh < 2; hh++) {
                float mx = -INFINITY;
                #pragma unroll
                for (int nf = 0; nf < 8; nf++) {
                    float v0 = sa[mf][nf][hh * 2]     * ATT_SCALE;
                    float v1 = sa[mf][nf][hh * 2 + 1] * ATT_SCALE;
                    sa[mf][nf][hh * 2]     = v0;
                    sa[mf][nf][hh * 2 + 1] = v1;
                    mx = fmaxf(mx, fmaxf(v0, v1));
                }
                mx = fmaxf(mx, __shfl_xor_sync(0xffffffffu, mx, 1));
                mx = fmaxf(mx, __shfl_xor_sync(0xffffffffu, mx, 2));
                float mnew = fmaxf(mrow[mf][hh], mx);
                float corr = __expf(mrow[mf][hh] - mnew);
                mrow[mf][hh] = mnew;
                float sum = 0.f;
                #pragma unroll
                for (int nf = 0; nf < 8; nf++) {
                    float p0 = __expf(sa[mf][nf][hh * 2]     - mnew);
                    float p1 = __expf(sa[mf][nf][hh * 2 + 1] - mnew);
                    sa[mf][nf][hh * 2]     = p0;
                    sa[mf][nf][hh * 2 + 1] = p1;
                    sum += p0 + p1;
                }
                sum += __shfl_xor_sync(0xffffffffu, sum, 1);
                sum += __shfl_xor_sync(0xffffffffu, sum, 2);
                lrow[mf][hh] = lrow[mf][hh] * corr + sum;
                #pragma unroll
                for (int nf = 0; nf < 6; nf++) {
                    oa[mf][nf][hh * 2]     *= corr;
                    oa[mf][nf][hh * 2 + 1] *= corr;
                }
            }
        }

        // pack P to half fragments
        uint32_t pa[2][8][2];
        #pragma unroll
        for (int mf = 0; mf < 2; mf++)
            #pragma unroll
            for (int nf = 0; nf < 8; nf++)
                #pragma unroll
                for (int hh = 0; hh < 2; hh++) {
                    __half2 hp = __floats2half2_rn(sa[mf][nf][hh * 2],
                                                   sa[mf][nf][hh * 2 + 1]);
                    pa[mf][nf][hh] = *(uint32_t*)&hp;
                }

        // O += P V
        #pragma unroll
        for (int j = 0; j < 4; j++) {
            uint32_t pfrag[2][4];
            #pragma unroll
            for (int mf = 0; mf < 2; mf++) {
                pfrag[mf][0] = pa[mf][2 * j][0];
                pfrag[mf][1] = pa[mf][2 * j][1];
                pfrag[mf][2] = pa[mf][2 * j + 1][0];
                pfrag[mf][3] = pa[mf][2 * j + 1][1];
            }
            #pragma unroll
            for (int ds = 0; ds < 3; ds++) {
                uint32_t vb[4];
                int row = j * 16 + (lane & 15);
                int ch  = (ds * 2 + (lane >> 4)) ^ (row & 7);
                ldm_x4t(vb, sV + (row * FA_LD + ch * 8) * 2);
                #pragma unroll
                for (int mf = 0; mf < 2; mf++) {
                    mma16816(oa[mf][2 * ds],     pfrag[mf], &vb[0]);
                    mma16816(oa[mf][2 * ds + 1], pfrag[mf], &vb[2]);
                }
            }
        }
    }

    // write out: x1 = x + O / l
    #pragma unroll
    for (int mf = 0; mf < 2; mf++) {
        #pragma unroll
        for (int hh = 0; hh < 2; hh++) {
            float inv = 1.0f / lrow[mf][hh];
            int row = q0blk + warp * 32 + mf * 16 + hh * 8 + gid;
            long base = ((long)b * NTOK + q_base + row) * DIM + h * HDIM;
            #pragma unroll
            for (int nf = 0; nf < 6; nf++) {
                int d = nf * 8 + tig * 2;
                float2 xr = *(const float2*)&x[base + d];
                float2 o;
                o.x = xr.x + oa[mf][nf][hh * 2]     * inv;
                o.y = xr.y + oa[mf][nf][hh * 2 + 1] * inv;
                *(float2*)&x1[base + d] = o;
            }
        }
    }
}

// ---------------- LayerNorm over last dim (384) ----------------
template<typename OUT>
__global__ __launch_bounds__(128)
void ln_kernel(const float* __restrict__ x, const float* __restrict__ g,
               const float* __restrict__ b, OUT* __restrict__ o)
{
    long row = blockIdx.x;
    const float* xp = x + row * DIM;
    int t = threadIdx.x;
    float v0 = xp[t], v1 = xp[t + 128], v2 = xp[t + 256];
    float s  = v0 + v1 + v2;
    float ss = v0 * v0 + v1 * v1 + v2 * v2;
    #pragma unroll
    for (int w = 16; w; w >>= 1) {
        s  += __shfl_xor_sync(0xffffffffu, s,  w);
        ss += __shfl_xor_sync(0xffffffffu, ss, w);
    }
    __shared__ float sm[4], sm2[4];
    if ((t & 31) == 0) { sm[t >> 5] = s; sm2[t >> 5] = ss; }
    __syncthreads();
    s  = sm[0]  + sm[1]  + sm[2]  + sm[3];
    ss = sm2[0] + sm2[1] + sm2[2] + sm2[3];
    float mean = s * (1.0f / DIM);
    float var  = ss * (1.0f / DIM) - mean * mean;
    float rs   = rsqrtf(var + 1e-5f);
    OUT* op = o + row * DIM;
    op[t]       = (OUT)((v0 - mean) * rs * g[t]       + b[t]);
    op[t + 128] = (OUT)((v1 - mean) * rs * g[t + 128] + b[t + 128]);
    op[t + 256] = (OUT)((v2 - mean) * rs * g[t + 256] + b[t + 256]);
}

// ---------------- depthwise 3x3 conv + inference BN (half out) -----------
__global__ __launch_bounds__(128)
void dwconv_kernel(const float* __restrict__ xn, __half* __restrict__ out,
                   const float* __restrict__ w,  const float* __restrict__ cb,
                   const float* __restrict__ g,  const float* __restrict__ bb,
                   int hw, int stride, int ohw,
                   int in_base, int out_base, int out_pitch)
{
    int t   = threadIdx.x;
    int pix = blockIdx.x;
    int b   = blockIdx.y;
    int oy = pix / ohw, ox = pix % ohw;

    float wr[3][9];
    #pragma unroll
    for (int u = 0; u < 3; u++)
        #pragma unroll
        for (int i = 0; i < 9; i++) wr[u][i] = w[(t + u * 128) * 9 + i];

    float a0 = 0.f, a1 = 0.f, a2 = 0.f;
    #pragma unroll
    for (int dy = 0; dy < 3; dy++) {
        int iy = oy * stride - 1 + dy;
        if ((unsigned)iy >= (unsigned)hw) continue;
        #pragma unroll
        for (int dx = 0; dx < 3; dx++) {
            int ix = ox * stride - 1 + dx;
            if ((unsigned)ix >= (unsigned)hw) continue;
            const float* p = xn + ((long)b * NTOK + in_base + iy * hw + ix) * DIM;
            int tap = dy * 3 + dx;
            a0 += p[t]       * wr[0][tap];
            a1 += p[t + 128] * wr[1][tap];
            a2 += p[t + 256] * wr[2][tap];
        }
    }
    float bn = rsqrtf(1.0f + 1e-5f);
    __half* op = out + ((long)b * out_pitch + out_base + pix) * DIM;
    op[t]       = __float2half((a0 + cb[t])       * (g[t]       * bn) + bb[t]);
    op[t + 128] = __float2half((a1 + cb[t + 128]) * (g[t + 128] * bn) + bb[t + 128]);
    op[t + 256] = __float2half((a2 + cb[t + 256]) * (g[t + 256] * bn) + bb[t + 256]);
}

// ---------------- fused f32 -> f16 conversion of all 5 weights -----------
__global__ __launch_bounds__(256)
void conv_f2h5(const float* s0, __half* d0, int n0,
               const float* s1, __half* d1, int n1,
               const float* s2, __half* d2, int n2,
               const float* s3, __half* d3, int n3,
               const float* s4, __half* d4, int n4)
{
    int i = blockIdx.x * 256 + threadIdx.x;
    if (i < n0) { d0[i] = __float2half(s0[i]); return; } i -= n0;
    if (i < n1) { d1[i] = __float2half(s1[i]); return; } i -= n1;
    if (i < n2) { d2[i] = __float2half(s2[i]); return; } i -= n2;
    if (i < n3) { d3[i] = __float2half(s3[i]); return; } i -= n3;
    if (i < n4) { d4[i] = __float2half(s4[i]); }
}

// ---------------- launch ----------------
extern "C" void kernel_launch(void* const* d_in, const int* /*in_sizes*/, int /*n_in*/,
                              void* d_out, int /*out_size*/)
{
    const float* x     = (const float*)d_in[0];
    const float* ln1_g = (const float*)d_in[1];
    const float* ln1_b = (const float*)d_in[2];
    const float* dwq_w = (const float*)d_in[3];
    const float* dwq_b = (const float*)d_in[4];
    const float* bnq_g = (const float*)d_in[5];
    const float* bnq_b = (const float*)d_in[6];
    const float* dwk_w = (const float*)d_in[7];
    const float* dwk_b = (const float*)d_in[8];
    const float* bnk_g = (const float*)d_in[9];
    const float* bnk_b = (const float*)d_in[10];
    const float* dwv_w = (const float*)d_in[11];
    const float* dwv_b = (const float*)d_in[12];
    const float* bnv_g = (const float*)d_in[13];
    const float* bnv_b = (const float*)d_in[14];
    const float* pq_w  = (const float*)d_in[15];
    const float* pq_b  = (const float*)d_in[16];
    const float* pk_w  = (const float*)d_in[17];
    const float* pk_b  = (const float*)d_in[18];
    const float* pv_w  = (const float*)d_in[19];
    const float* pv_b  = (const float*)d_in[20];
    const float* ln2_g = (const float*)d_in[21];
    const float* ln2_b = (const float*)d_in[22];
    const float* ff1_w = (const float*)d_in[23];
    const float* ff1_b = (const float*)d_in[24];
    const float* ff2_w = (const float*)d_in[25];
    const float* ff2_b = (const float*)d_in[26];
    float* out = (float*)d_out;

    float *xn, *x1;
    __half *qtok, *ktok, *vtok, *Q, *K, *V, *ln2, *ff;
    __half *wq, *wk, *wv, *w1, *w2;
    cudaGetSymbolAddress((void**)&xn,   g_xn);
    cudaGetSymbolAddress((void**)&x1,   g_x1);
    cudaGetSymbolAddress((void**)&qtok, h_qtok);
    cudaGetSymbolAddress((void**)&ktok, h_ktok);
    cudaGetSymbolAddress((void**)&vtok, h_vtok);
    cudaGetSymbolAddress((void**)&Q,    h_Q);
    cudaGetSymbolAddress((void**)&K,    h_K);
    cudaGetSymbolAddress((void**)&V,    h_V);
    cudaGetSymbolAddress((void**)&ln2,  h_ln2);
    cudaGetSymbolAddress((void**)&ff,   h_ff);
    cudaGetSymbolAddress((void**)&wq,   h_wq);
    cudaGetSymbolAddress((void**)&wk,   h_wk);
    cudaGetSymbolAddress((void**)&wv,   h_wv);
    cudaGetSymbolAddress((void**)&w1,   h_w1);
    cudaGetSymbolAddress((void**)&w2,   h_w2);

    // 0) all weight conversions in one launch
    {
        int n0 = DIM * DIM, n3 = FFD * DIM, n4 = DIM * FFD;
        int total = 3 * n0 + n3 + n4;
        conv_f2h5<<<(total + 255) / 256, 256>>>(pq_w, wq, n0, pk_w, wk, n0,
                                                pv_w, wv, n0, ff1_w, w1, n3,
                                                ff2_w, w2, n4);
    }

    // 1) LN1 (fp32 out for conv input)
    ln_kernel<float><<<BATCH * NTOK, 128>>>(x, ln1_g, ln1_b, xn);

    // 2) depthwise convs + BN (fp16 out)
    dwconv_kernel<<<dim3(1024, BATCH), 128>>>(xn, qtok, dwq_w, dwq_b, bnq_g, bnq_b,
                                              32, 1, 32, 0, 0, NTOK);
    dwconv_kernel<<<dim3(256, BATCH), 128>>>(xn, ktok, dwk_w, dwk_b, bnk_g, bnk_b,
                                             32, 2, 16, 0, 0, KVMIX);
    dwconv_kernel<<<dim3(256, BATCH), 128>>>(xn, vtok, dwv_w, dwv_b, bnv_g, bnv_b,
                                             32, 2, 16, 0, 0, KVMIX);
    dwconv_kernel<<<dim3(256, BATCH), 128>>>(xn, qtok, dwq_w, dwq_b, bnq_g, bnq_b,
                                             16, 1, 16, NSRCH, NSRCH, NTOK);
    dwconv_kernel<<<dim3(64, BATCH), 128>>>(xn, ktok, dwk_w, dwk_b, bnk_g, bnk_b,
                                            16, 2, 8, NSRCH, 256, KVMIX);
    dwconv_kernel<<<dim3(64, BATCH), 128>>>(xn, vtok, dwv_w, dwv_b, bnv_g, bnv_b,
                                            16, 2, 8, NSRCH, 256, KVMIX);

    // 3) projections -> fp16 Q/K/V
    gemm_h<0><<<dim3(DIM / BNH, (BATCH * NTOK) / BMH), 256>>>(
        qtok, wq, pq_b, nullptr, Q, DIM, DIM, DIM, DIM, DIM);
    gemm_h<0><<<dim3(DIM / BNH, (BATCH * KVMIX) / BMH), 256>>>(
        ktok, wk, pk_b, nullptr, K, DIM, DIM, DIM, DIM, DIM);
    gemm_h<0><<<dim3(DIM / BNH, (BATCH * KVMIX) / BMH), 256>>>(
        vtok, wv, pv_b, nullptr, V, DIM, DIM, DIM, DIM, DIM);

    // 4) fused flash attention (writes x1 = x + attn)
    attn_fa<<<dim3(NSRCH / 128, NHEAD, BATCH), 128>>>(Q, K, V, x, x1, 0, 0, KVMIX);
    attn_fa<<<dim3((NTOK - NSRCH) / 128, NHEAD, BATCH), 128>>>(Q, K, V, x, x1,
                                                               NSRCH, 256, 64);

    // 5) LN2 (fp16 out) + FFN + residual into d_out
    ln_kernel<__half><<<BATCH * NTOK, 128>>>(x1, ln2_g, ln2_b, ln2);
    gemm_h<1><<<dim3(FFD / BNH, (BATCH * NTOK) / BMH), 256>>>(
        ln2, w1, ff1_b, nullptr, ff, DIM, FFD, DIM, DIM, FFD);
    gemm_h<2><<<dim3(DIM / BNH, (BATCH * NTOK) / BMH), 256>>>(
        ff, w2, ff2_b, x1, out, FFD, DIM, FFD, FFD, DIM);
}

// round 8
// speedup vs baseline: 1.1840x; 1.1840x over previous
#include <cuda_runtime.h>
#include <cuda_fp16.h>
#include <math.h>
#include <stdint.h>

// ---------------- problem constants ----------------
#define BATCH   32
#define NTOK    1280
#define DIM     384
#define NHEAD   8
#define HDIM    48
#define NSRCH   1024
#define KVMIX   320
#define FFD     1536
#define ATT_SCALE 0.14433756729740643f   // 1/sqrt(48)

// ---------------- scratch (device globals; no allocation allowed) --------
__device__ float  g_xn [BATCH * NTOK * DIM];
__device__ float  g_x1 [BATCH * NTOK * DIM];
__device__ __half h_qtok[BATCH * NTOK * DIM];
__device__ __half h_ktok[BATCH * KVMIX * DIM];
__device__ __half h_vtok[BATCH * KVMIX * DIM];
__device__ __half h_Q  [BATCH * NTOK * DIM];
__device__ __half h_K  [BATCH * KVMIX * DIM];
__device__ __half h_V  [BATCH * KVMIX * DIM];
__device__ __half h_ln2[BATCH * NTOK * DIM];
__device__ __half h_ff [BATCH * NTOK * FFD];
__device__ __half h_wq [DIM * DIM];
__device__ __half h_wk [DIM * DIM];
__device__ __half h_wv [DIM * DIM];
__device__ __half h_w1 [FFD * DIM];
__device__ __half h_w2 [DIM * FFD];

// ================= small helpers =================
__device__ __forceinline__ uint32_t smem_u32(const void* p)
{
    uint32_t a;
    asm("{ .reg .u64 t; cvta.to.shared.u64 t, %1; cvt.u32.u64 %0, t; }"
        : "=r"(a) : "l"(p));
    return a;
}

__device__ __forceinline__ void cpasync16(uint32_t dst, const void* src)
{
    asm volatile("cp.async.cg.shared.global [%0], [%1], 16;"
                 :: "r"(dst), "l"(src));
}

__device__ __forceinline__ void ldm_x4(uint32_t* r, uint32_t addr)
{
    asm volatile("ldmatrix.sync.aligned.m8n8.x4.shared.b16 {%0,%1,%2,%3}, [%4];"
                 : "=r"(r[0]), "=r"(r[1]), "=r"(r[2]), "=r"(r[3]) : "r"(addr));
}

__device__ __forceinline__ void ldm_x4t(uint32_t* r, uint32_t addr)
{
    asm volatile("ldmatrix.sync.aligned.m8n8.x4.trans.shared.b16 {%0,%1,%2,%3}, [%4];"
                 : "=r"(r[0]), "=r"(r[1]), "=r"(r[2]), "=r"(r[3]) : "r"(addr));
}

__device__ __forceinline__ void mma16816(float* d, const uint32_t* a, const uint32_t* b)
{
    asm volatile(
        "mma.sync.aligned.m16n8k16.row.col.f32.f16.f16.f32 "
        "{%0,%1,%2,%3}, {%4,%5,%6,%7}, {%8,%9}, {%0,%1,%2,%3};"
        : "+f"(d[0]), "+f"(d[1]), "+f"(d[2]), "+f"(d[3])
        : "r"(a[0]), "r"(a[1]), "r"(a[2]), "r"(a[3]), "r"(b[0]), "r"(b[1]));
}

// ================= fp16 tensor-core GEMM (proj / FFN) =================
// C = A(MxK) * B(NxK)^T, fp16 in, fp32 acc.
// Block 128x64x32, 8 warps (4m x 2n), warp tile 32x32.
// 3-stage cp.async pipeline, ONE barrier per k-tile.
// All dims divide tiles exactly at every call site.
// EPI: 0 bias->half, 1 bias+gelu->half, 2 bias+res->float
#define BMH 128
#define BNH 64
#define BKH 32
#define NST 3
#define LDS_A 40   // halfs per smem row (80B); chunk-xor swizzled

template<int EPI>
__global__ __launch_bounds__(256)
void gemm_h(const __half* __restrict__ A, const __half* __restrict__ Bw,
            const float* __restrict__ bias, const float* __restrict__ res,
            void* __restrict__ Cv, int K, int Nn,
            int lda, int ldb, int ldc)
{
    __shared__ __half As[NST][BMH * LDS_A];
    __shared__ __half Bs[NST][BNH * LDS_A];

    int tid  = threadIdx.x;
    int warp = tid >> 5, lane = tid & 31;
    int wm = warp >> 1, wn = warp & 1;
    int cn = blockIdx.x * BNH;
    int cm = blockIdx.y * BMH;

    const __half* Ab = A  + (long)cm * lda;
    const __half* Bb = Bw + (long)cn * ldb;

    uint32_t sA[NST], sB[NST];
    #pragma unroll
    for (int s = 0; s < NST; s++) { sA[s] = smem_u32(As[s]); sB[s] = smem_u32(Bs[s]); }

    // one stage fill: A 512 chunks (2/thread), B 256 chunks (1/thread)
    auto fill = [&](int st, int kt) {
        int k0 = kt * BKH;
        #pragma unroll
        for (int i = 0; i < 2; i++) {
            int c = tid + i * 256;
            int row = c >> 2, ch = c & 3;
            uint32_t dst = sA[st] + (row * LDS_A + ((ch ^ (row & 3)) * 8)) * 2;
            cpasync16(dst, Ab + (long)row * lda + k0 + ch * 8);
        }
        {
            int n = tid >> 2, ch = tid & 3;
            uint32_t dst = sB[st] + (n * LDS_A + ((ch ^ (n & 3)) * 8)) * 2;
            cpasync16(dst, Bb + (long)n * ldb + k0 + ch * 8);
        }
        asm volatile("cp.async.commit_group;" ::: "memory");
    };

    int l15 = lane & 15, l7 = lane & 7, l3 = lane & 3;
    int achunk[2], bchunk[2];
    #pragma unroll
    for (int ks = 0; ks < 2; ks++) {
        achunk[ks] = (((lane >> 4) + 2 * ks) ^ l3) * 8;
        bchunk[ks] = ((((lane >> 3) & 1) + 2 * ks) ^ l3) * 8;
    }
    int arow[2], brow[2];
    #pragma unroll
    for (int f = 0; f < 2; f++)
        arow[f] = (wm * 32 + f * 16 + l15) * LDS_A;
    #pragma unroll
    for (int p = 0; p < 2; p++)
        brow[p] = (wn * 32 + p * 16 + ((lane >> 4) & 1) * 8 + l7) * LDS_A;

    float acc[2][4][4];
    #pragma unroll
    for (int i = 0; i < 2; i++)
        #pragma unroll
        for (int j = 0; j < 4; j++)
            #pragma unroll
            for (int q = 0; q < 4; q++) acc[i][j][q] = 0.f;

    int T = K / BKH;          // >= 12 at every call site
    fill(0, 0);
    fill(1, 1);

    for (int t = 0; t < T; t++) {
        if (t == T - 1) asm volatile("cp.async.wait_group 0;" ::: "memory");
        else            asm volatile("cp.async.wait_group 1;" ::: "memory");
        __syncthreads();
        if (t + 2 < T) fill((t + 2) % NST, t + 2);

        int st = t % NST;
        #pragma unroll
        for (int ks = 0; ks < 2; ks++) {
            uint32_t ar[2][4], br[2][4];
            #pragma unroll
            for (int f = 0; f < 2; f++)
                ldm_x4(ar[f], sA[st] + (arow[f] + achunk[ks]) * 2);
            #pragma unroll
            for (int p = 0; p < 2; p++)
                ldm_x4(br[p], sB[st] + (brow[p] + bchunk[ks]) * 2);
            #pragma unroll
            for (int mf = 0; mf < 2; mf++)
                #pragma unroll
                for (int nf = 0; nf < 4; nf++) {
                    uint32_t bf[2] = { br[nf >> 1][(nf & 1) * 2],
                                       br[nf >> 1][(nf & 1) * 2 + 1] };
                    mma16816(acc[mf][nf], ar[mf], bf);
                }
        }
    }

    int gid = lane >> 2, cpos = (lane & 3) * 2;
    #pragma unroll
    for (int mf = 0; mf < 2; mf++) {
        #pragma unroll
        for (int nf = 0; nf < 4; nf++) {
            int col = cn + wn * 32 + nf * 8 + cpos;
            long r0 = cm + wm * 32 + mf * 16 + gid;
            #pragma unroll
            for (int hh = 0; hh < 2; hh++) {
                long idx = (r0 + hh * 8) * (long)ldc + col;
                float v0 = acc[mf][nf][hh * 2 + 0];
                float v1 = acc[mf][nf][hh * 2 + 1];
                v0 += bias[col]; v1 += bias[col + 1];
                if (EPI == 1) { v0 *= normcdff(v0); v1 *= normcdff(v1); }
                if (EPI == 2) {
                    float2 r2 = *(const float2*)&res[idx];
                    v0 += r2.x; v1 += r2.y;
                    float2 o; o.x = v0; o.y = v1;
                    *(float2*)&((float*)Cv)[idx] = o;
                } else {
                    *(__half2*)&((__half*)Cv)[idx] = __floats2half2_rn(v0, v1);
                }
            }
        }
    }
}

// ================= fused flash attention (legacy mma) ====================
// One CTA = 128 query rows of one (batch, head). 4 warps, warp = 32 q rows.
// K/V tiles 64 x 48 (64-half rows, chunk-xor swizzle).
#define FA_LD 64   // halfs per smem row (128B)

__global__ __launch_bounds__(128)
void attn_fa(const __half* __restrict__ Q, const __half* __restrict__ Kh,
             const __half* __restrict__ Vh, const float* __restrict__ x,
             float* __restrict__ x1, int q_base, int kv_base, int kv_len)
{
    __shared__ __half Qs[128 * FA_LD];
    __shared__ __half Ks[64 * FA_LD];
    __shared__ __half Vs[64 * FA_LD];

    int tid = threadIdx.x;
    int warp = tid >> 5, lane = tid & 31;
    int gid = lane >> 2, tig = lane & 3;
    int b = blockIdx.z, h = blockIdx.y;
    int q0blk = blockIdx.x * 128;

    const __half* Qg = Q + ((long)b * NTOK + q_base + q0blk) * DIM + h * HDIM;
    const __half* Kg = Kh + ((long)b * KVMIX + kv_base) * DIM + h * HDIM;
    const __half* Vg = Vh + ((long)b * KVMIX + kv_base) * DIM + h * HDIM;

    uint32_t sQ = smem_u32(Qs), sK = smem_u32(Ks), sV = smem_u32(Vs);

    // load Q tile (128 rows x 6 chunks of 16B)
    {
        int row = tid;
        #pragma unroll
        for (int c = 0; c < 6; c++) {
            uint32_t dst = sQ + (row * FA_LD + ((c ^ (row & 7)) * 8)) * 2;
            cpasync16(dst, Qg + (long)row * DIM + c * 8);
        }
    }
    asm volatile("cp.async.commit_group;" ::: "memory");
    asm volatile("cp.async.wait_group 0;" ::: "memory");
    __syncthreads();

    // Q fragments: qa[ks][mf][4]
    uint32_t qa[3][2][4];
    {
        int qrow_base = warp * 32;
        #pragma unroll
        for (int ks = 0; ks < 3; ks++)
            #pragma unroll
            for (int mf = 0; mf < 2; mf++) {
                int row = qrow_base + mf * 16 + (lane & 15);
                int ch  = (ks * 2 + (lane >> 4)) ^ (row & 7);
                ldm_x4(qa[ks][mf], sQ + (row * FA_LD + ch * 8) * 2);
            }
    }

    float oa[2][6][4];
    #pragma unroll
    for (int i = 0; i < 2; i++)
        #pragma unroll
        for (int j = 0; j < 6; j++)
            #pragma unroll
            for (int q = 0; q < 4; q++) oa[i][j][q] = 0.f;
    float mrow[2][2] = { {-INFINITY, -INFINITY}, {-INFINITY, -INFINITY} };
    float lrow[2][2] = { {0.f, 0.f}, {0.f, 0.f} };

    int nc = kv_len >> 6;
    for (int c = 0; c < nc; c++) {
        __syncthreads();
        // load K, V tiles: 384 chunks each, 128 threads x 3
        #pragma unroll
        for (int i = 0; i < 3; i++) {
            int idx = tid * 3 + i;
            int row = idx / 6, ch = idx % 6;
            long go = ((long)(c * 64 + row)) * DIM + ch * 8;
            uint32_t sw = (row * FA_LD + ((ch ^ (row & 7)) * 8)) * 2;
            cpasync16(sK + sw, Kg + go);
            cpasync16(sV + sw, Vg + go);
        }
        asm volatile("cp.async.commit_group;" ::: "memory");
        asm volatile("cp.async.wait_group 0;" ::: "memory");
        __syncthreads();

        // S = Q K^T  (warp's 32 rows x 64 cols)
        float sa[2][8][4];
        #pragma unroll
        for (int i = 0; i < 2; i++)
            #pragma unroll
            for (int j = 0; j < 8; j++)
                #pragma unroll
                for (int q = 0; q < 4; q++) sa[i][j][q] = 0.f;

        #pragma unroll
        for (int ks = 0; ks < 3; ks++) {
            #pragma unroll
            for (int g = 0; g < 4; g++) {
                uint32_t kb[4];
                int row = g * 16 + (lane & 7) + ((lane >> 4) & 1) * 8;
                int ch  = (ks * 2 + ((lane >> 3) & 1)) ^ (row & 7);
                ldm_x4(kb, sK + (row * FA_LD + ch * 8) * 2);
                #pragma unroll
                for (int mf = 0; mf < 2; mf++) {
                    mma16816(sa[mf][2 * g],     qa[ks][mf], &kb[0]);
                    mma16816(sa[mf][2 * g + 1], qa[ks][mf], &kb[2]);
                }
            }
        }

        // online softmax
        #pragma unroll
        for (int mf = 0; mf < 2; mf++) {
            #pragma unroll
            for (int hh = 0; hh < 2; hh++) {
                float mx = -INFINITY;
                #pragma unroll
                for (int nf = 0; nf < 8; nf++) {
                    float v0 = sa[mf][nf][hh * 2]     * ATT_SCALE;
                    float v1 = sa[mf][nf][hh * 2 + 1] * ATT_SCALE;
                    sa[mf][nf][hh * 2]     = v0;
                    sa[mf][nf][hh * 2 + 1] = v1;
                    mx = fmaxf(mx, fmaxf(v0, v1));
                }
                mx = fmaxf(mx, __shfl_xor_sync(0xffffffffu, mx, 1));
                mx = fmaxf(mx, __shfl_xor_sync(0xffffffffu, mx, 2));
                float mnew = fmaxf(mrow[mf][hh], mx);
                float corr = __expf(mrow[mf][hh] - mnew);
                mrow[mf][hh] = mnew;
                float sum = 0.f;
                #pragma unroll
                for (int nf = 0; nf < 8; nf++) {
                    float p0 = __expf(sa[mf][nf][hh * 2]     - mnew);
                    float p1 = __expf(sa[mf][nf][hh * 2 + 1] - mnew);
                    sa[mf][nf][hh * 2]     = p0;
                    sa[mf][nf][hh * 2 + 1] = p1;
                    sum += p0 + p1;
                }
                sum += __shfl_xor_sync(0xffffffffu, sum, 1);
                sum += __shfl_xor_sync(0xffffffffu, sum, 2);
                lrow[mf][hh] = lrow[mf][hh] * corr + sum;
                #pragma unroll
                for (int nf = 0; nf < 6; nf++) {
                    oa[mf][nf][hh * 2]     *= corr;
                    oa[mf][nf][hh * 2 + 1] *= corr;
                }
            }
        }

        // pack P to half fragments
        uint32_t pa[2][8][2];
        #pragma unroll
        for (int mf = 0; mf < 2; mf++)
            #pragma unroll
            for (int nf = 0; nf < 8; nf++)
                #pragma unroll
                for (int hh = 0; hh < 2; hh++) {
                    __half2 hp = __floats2half2_rn(sa[mf][nf][hh * 2],
                                                   sa[mf][nf][hh * 2 + 1]);
                    pa[mf][nf][hh] = *(uint32_t*)&hp;
                }

        // O += P V
        #pragma unroll
        for (int j = 0; j < 4; j++) {
            uint32_t pfrag[2][4];
            #pragma unroll
            for (int mf = 0; mf < 2; mf++) {
                pfrag[mf][0] = pa[mf][2 * j][0];
                pfrag[mf][1] = pa[mf][2 * j][1];
                pfrag[mf][2] = pa[mf][2 * j + 1][0];
                pfrag[mf][3] = pa[mf][2 * j + 1][1];
            }
            #pragma unroll
            for (int ds = 0; ds < 3; ds++) {
                uint32_t vb[4];
                int row = j * 16 + (lane & 15);
                int ch  = (ds * 2 + (lane >> 4)) ^ (row & 7);
                ldm_x4t(vb, sV + (row * FA_LD + ch * 8) * 2);
                #pragma unroll
                for (int mf = 0; mf < 2; mf++) {
                    mma16816(oa[mf][2 * ds],     pfrag[mf], &vb[0]);
                    mma16816(oa[mf][2 * ds + 1], pfrag[mf], &vb[2]);
                }
            }
        }
    }

    // write out: x1 = x + O / l
    #pragma unroll
    for (int mf = 0; mf < 2; mf++) {
        #pragma unroll
        for (int hh = 0; hh < 2; hh++) {
            float inv = 1.0f / lrow[mf][hh];
            int row = q0blk + warp * 32 + mf * 16 + hh * 8 + gid;
            long base = ((long)b * NTOK + q_base + row) * DIM + h * HDIM;
            #pragma unroll
            for (int nf = 0; nf < 6; nf++) {
                int d = nf * 8 + tig * 2;
                float2 xr = *(const float2*)&x[base + d];
                float2 o;
                o.x = xr.x + oa[mf][nf][hh * 2]     * inv;
                o.y = xr.y + oa[mf][nf][hh * 2 + 1] * inv;
                *(float2*)&x1[base + d] = o;
            }
        }
    }
}

// ---------------- LayerNorm over last dim (384) ----------------
template<typename OUT>
__global__ __launch_bounds__(128)
void ln_kernel(const float* __restrict__ x, const float* __restrict__ g,
               const float* __restrict__ b, OUT* __restrict__ o)
{
    long row = blockIdx.x;
    const float* xp = x + row * DIM;
    int t = threadIdx.x;
    float v0 = xp[t], v1 = xp[t + 128], v2 = xp[t + 256];
    float s  = v0 + v1 + v2;
    float ss = v0 * v0 + v1 * v1 + v2 * v2;
    #pragma unroll
    for (int w = 16; w; w >>= 1) {
        s  += __shfl_xor_sync(0xffffffffu, s,  w);
        ss += __shfl_xor_sync(0xffffffffu, ss, w);
    }
    __shared__ float sm[4], sm2[4];
    if ((t & 31) == 0) { sm[t >> 5] = s; sm2[t >> 5] = ss; }
    __syncthreads();
    s  = sm[0]  + sm[1]  + sm[2]  + sm[3];
    ss = sm2[0] + sm2[1] + sm2[2] + sm2[3];
    float mean = s * (1.0f / DIM);
    float var  = ss * (1.0f / DIM) - mean * mean;
    float rs   = rsqrtf(var + 1e-5f);
    OUT* op = o + row * DIM;
    op[t]       = (OUT)((v0 - mean) * rs * g[t]       + b[t]);
    op[t + 128] = (OUT)((v1 - mean) * rs * g[t + 128] + b[t + 128]);
    op[t + 256] = (OUT)((v2 - mean) * rs * g[t + 256] + b[t + 256]);
}

// ---------------- depthwise 3x3 conv + inference BN (half out) -----------
__global__ __launch_bounds__(128)
void dwconv_kernel(const float* __restrict__ xn, __half* __restrict__ out,
                   const float* __restrict__ w,  const float* __restrict__ cb,
                   const float* __restrict__ g,  const float* __restrict__ bb,
                   int hw, int stride, int ohw,
                   int in_base, int out_base, int out_pitch)
{
    int t   = threadIdx.x;
    int pix = blockIdx.x;
    int b   = blockIdx.y;
    int oy = pix / ohw, ox = pix % ohw;

    float wr[3][9];
    #pragma unroll
    for (int u = 0; u < 3; u++)
        #pragma unroll
        for (int i = 0; i < 9; i++) wr[u][i] = w[(t + u * 128) * 9 + i];

    float a0 = 0.f, a1 = 0.f, a2 = 0.f;
    #pragma unroll
    for (int dy = 0; dy < 3; dy++) {
        int iy = oy * stride - 1 + dy;
        if ((unsigned)iy >= (unsigned)hw) continue;
        #pragma unroll
        for (int dx = 0; dx < 3; dx++) {
            int ix = ox * stride - 1 + dx;
            if ((unsigned)ix >= (unsigned)hw) continue;
            const float* p = xn + ((long)b * NTOK + in_base + iy * hw + ix) * DIM;
            int tap = dy * 3 + dx;
            a0 += p[t]       * wr[0][tap];
            a1 += p[t + 128] * wr[1][tap];
            a2 += p[t + 256] * wr[2][tap];
        }
    }
    float bn = rsqrtf(1.0f + 1e-5f);
    __half* op = out + ((long)b * out_pitch + out_base + pix) * DIM;
    op[t]       = __float2half((a0 + cb[t])       * (g[t]       * bn) + bb[t]);
    op[t + 128] = __float2half((a1 + cb[t + 128]) * (g[t + 128] * bn) + bb[t + 128]);
    op[t + 256] = __float2half((a2 + cb[t + 256]) * (g[t + 256] * bn) + bb[t + 256]);
}

// ---------------- fused f32 -> f16 conversion of all 5 weights -----------
__global__ __launch_bounds__(256)
void conv_f2h5(const float* s0, __half* d0, int n0,
               const float* s1, __half* d1, int n1,
               const float* s2, __half* d2, int n2,
               const float* s3, __half* d3, int n3,
               const float* s4, __half* d4, int n4)
{
    int i = blockIdx.x * 256 + threadIdx.x;
    if (i < n0) { d0[i] = __float2half(s0[i]); return; } i -= n0;
    if (i < n1) { d1[i] = __float2half(s1[i]); return; } i -= n1;
    if (i < n2) { d2[i] = __float2half(s2[i]); return; } i -= n2;
    if (i < n3) { d3[i] = __float2half(s3[i]); return; } i -= n3;
    if (i < n4) { d4[i] = __float2half(s4[i]); }
}

// ---------------- launch ----------------
extern "C" void kernel_launch(void* const* d_in, const int* /*in_sizes*/, int /*n_in*/,
                              void* d_out, int /*out_size*/)
{
    const float* x     = (const float*)d_in[0];
    const float* ln1_g = (const float*)d_in[1];
    const float* ln1_b = (const float*)d_in[2];
    const float* dwq_w = (const float*)d_in[3];
    const float* dwq_b = (const float*)d_in[4];
    const float* bnq_g = (const float*)d_in[5];
    const float* bnq_b = (const float*)d_in[6];
    const float* dwk_w = (const float*)d_in[7];
    const float* dwk_b = (const float*)d_in[8];
    const float* bnk_g = (const float*)d_in[9];
    const float* bnk_b = (const float*)d_in[10];
    const float* dwv_w = (const float*)d_in[11];
    const float* dwv_b = (const float*)d_in[12];
    const float* bnv_g = (const float*)d_in[13];
    const float* bnv_b = (const float*)d_in[14];
    const float* pq_w  = (const float*)d_in[15];
    const float* pq_b  = (const float*)d_in[16];
    const float* pk_w  = (const float*)d_in[17];
    const float* pk_b  = (const float*)d_in[18];
    const float* pv_w  = (const float*)d_in[19];
    const float* pv_b  = (const float*)d_in[20];
    const float* ln2_g = (const float*)d_in[21];
    const float* ln2_b = (const float*)d_in[22];
    const float* ff1_w = (const float*)d_in[23];
    const float* ff1_b = (const float*)d_in[24];
    const float* ff2_w = (const float*)d_in[25];
    const float* ff2_b = (const float*)d_in[26];
    float* out = (float*)d_out;

    float *xn, *x1;
    __half *qtok, *ktok, *vtok, *Q, *K, *V, *ln2, *ff;
    __half *wq, *wk, *wv, *w1, *w2;
    cudaGetSymbolAddress((void**)&xn,   g_xn);
    cudaGetSymbolAddress((void**)&x1,   g_x1);
    cudaGetSymbolAddress((void**)&qtok, h_qtok);
    cudaGetSymbolAddress((void**)&ktok, h_ktok);
    cudaGetSymbolAddress((void**)&vtok, h_vtok);
    cudaGetSymbolAddress((void**)&Q,    h_Q);
    cudaGetSymbolAddress((void**)&K,    h_K);
    cudaGetSymbolAddress((void**)&V,    h_V);
    cudaGetSymbolAddress((void**)&ln2,  h_ln2);
    cudaGetSymbolAddress((void**)&ff,   h_ff);
    cudaGetSymbolAddress((void**)&wq,   h_wq);
    cudaGetSymbolAddress((void**)&wk,   h_wk);
    cudaGetSymbolAddress((void**)&wv,   h_wv);
    cudaGetSymbolAddress((void**)&w1,   h_w1);
    cudaGetSymbolAddress((void**)&w2,   h_w2);

    // launch 0: all weight conversions
    {
        int n0 = DIM * DIM, n3 = FFD * DIM, n4 = DIM * FFD;
        int total = 3 * n0 + n3 + n4;
        conv_f2h5<<<(total + 255) / 256, 256>>>(pq_w, wq, n0, pk_w, wk, n0,
                                                pv_w, wv, n0, ff1_w, w1, n3,
                                                ff2_w, w2, n4);
    }

    // launch 1: LN1 (fp32 out for conv input)
    ln_kernel<float><<<BATCH * NTOK, 128>>>(x, ln1_g, ln1_b, xn);

    // launches 2-3: Q-branch convs (completes qtok)
    dwconv_kernel<<<dim3(1024, BATCH), 128>>>(xn, qtok, dwq_w, dwq_b, bnq_g, bnq_b,
                                              32, 1, 32, 0, 0, NTOK);
    dwconv_kernel<<<dim3(256, BATCH), 128>>>(xn, qtok, dwq_w, dwq_b, bnq_g, bnq_b,
                                             16, 1, 16, NSRCH, NSRCH, NTOK);
    // launch 4: K-search conv
    dwconv_kernel<<<dim3(256, BATCH), 128>>>(xn, ktok, dwk_w, dwk_b, bnk_g, bnk_b,
                                             32, 2, 16, 0, 0, KVMIX);
    // launch 5 (ncu -s 5 -c 1 profiles THIS): Q projection GEMM
    gemm_h<0><<<dim3(DIM / BNH, (BATCH * NTOK) / BMH), 256>>>(
        qtok, wq, pq_b, nullptr, Q, DIM, DIM, DIM, DIM, DIM);

    // launches 6-8: remaining convs
    dwconv_kernel<<<dim3(64, BATCH), 128>>>(xn, ktok, dwk_w, dwk_b, bnk_g, bnk_b,
                                            16, 2, 8, NSRCH, 256, KVMIX);
    dwconv_kernel<<<dim3(256, BATCH), 128>>>(xn, vtok, dwv_w, dwv_b, bnv_g, bnv_b,
                                             32, 2, 16, 0, 0, KVMIX);
    dwconv_kernel<<<dim3(64, BATCH), 128>>>(xn, vtok, dwv_w, dwv_b, bnv_g, bnv_b,
                                            16, 2, 8, NSRCH, 256, KVMIX);

    // launches 9-10: K/V projections
    gemm_h<0><<<dim3(DIM / BNH, (BATCH * KVMIX) / BMH), 256>>>(
        ktok, wk, pk_b, nullptr, K, DIM, DIM, DIM, DIM, DIM);
    gemm_h<0><<<dim3(DIM / BNH, (BATCH * KVMIX) / BMH), 256>>>(
        vtok, wv, pv_b, nullptr, V, DIM, DIM, DIM, DIM, DIM);

    // launches 11-12: fused flash attention (writes x1 = x + attn)
    attn_fa<<<dim3(NSRCH / 128, NHEAD, BATCH), 128>>>(Q, K, V, x, x1, 0, 0, KVMIX);
    attn_fa<<<dim3((NTOK - NSRCH) / 128, NHEAD, BATCH), 128>>>(Q, K, V, x, x1,
                                                               NSRCH, 256, 64);

    // launches 13-15: LN2 + FFN + residual into d_out
    ln_kernel<__half><<<BATCH * NTOK, 128>>>(x1, ln2_g, ln2_b, ln2);
    gemm_h<1><<<dim3(FFD / BNH, (BATCH * NTOK) / BMH), 256>>>(
        ln2, w1, ff1_b, nullptr, ff, DIM, FFD, DIM, DIM, FFD);
    gemm_h<2><<<dim3(DIM / BNH, (BATCH * NTOK) / BMH), 256>>>(
        ff, w2, ff2_b, x1, out, FFD, DIM, FFD, FFD, DIM);
}